// round 4
// baseline (speedup 1.0000x reference)
#include <cuda_runtime.h>

// NCM R4: R2 layout + SMEM-duplicated weights (no dup2 in hot loop) +
// explicitly software-pipelined inner loop (half-batch interleave, next-k
// prefetch). 128 CTAs x 256 threads, warp = 32 samples as 16 f32x2 pairs,
// lane owns 2 output cols.

#define TPB    256
#define NBLK   128
#define NNODES 32

typedef unsigned long long u64;

__device__ __forceinline__ u64 fma2(u64 a, u64 b, u64 c) {
    u64 d; asm("fma.rn.f32x2 %0,%1,%2,%3;" : "=l"(d) : "l"(a), "l"(b), "l"(c));
    return d;
}
__device__ __forceinline__ u64 dup2(float x) {
    u64 d; asm("mov.b64 %0,{%1,%1};" : "=l"(d) : "f"(x)); return d;
}
__device__ __forceinline__ void unpk(u64 a, float& lo, float& hi) {
    asm("mov.b64 {%0,%1},%2;" : "=f"(lo), "=f"(hi) : "l"(a));
}
__device__ __forceinline__ u64 pk(float lo, float hi) {
    u64 d; asm("mov.b64 %0,{%1,%2};" : "=l"(d) : "f"(lo), "f"(hi)); return d;
}
__device__ __forceinline__ u64 relu2(u64 a) {
    float lo, hi; unpk(a, lo, hi);
    return pk(fmaxf(lo, 0.0f), fmaxf(hi, 0.0f));
}

// u64-unit SMEM offsets
#define W1D 0                    // dup'd w1: 80*64 u64
#define W2D 5120                 // dup'd w2: 64*64 u64
#define W3F 9216                 // w3 floats: 64*16 = 512 u64
#define B1F 9728                 // b1: 64 f = 32 u64
#define B2F 9760
#define B3F 9792                 // b3: 16 f = 8 u64
#define ACT 9800
#define IN_STR 82                // per-pair row: [0..63] parent ring, [64..79] u
#define H_STR  64
#define WARP_U64 (16 * IN_STR + 16 * H_STR)   // 2336
#define SMEM_BYTES ((ACT + 8 * WARP_U64 + 16) * 8)   // 228032

__global__ void __launch_bounds__(TPB, 1) ncm_kernel(
    const float* __restrict__ u,
    const float* __restrict__ w_r1, const float* __restrict__ b_r1,
    const float* __restrict__ w_r2, const float* __restrict__ b_r2,
    const float* __restrict__ w_r3, const float* __restrict__ b_r3,
    const float* __restrict__ w_i1, const float* __restrict__ b_i1,
    const float* __restrict__ w_i2, const float* __restrict__ b_i2,
    const float* __restrict__ w_i3, const float* __restrict__ b_i3,
    float* __restrict__ out)
{
    extern __shared__ u64 sm[];
    u64* w1d = sm + W1D;
    u64* w2d = sm + W2D;
    float* s_w3 = (float*)(sm + W3F);
    float* s_b1 = (float*)(sm + B1F);
    float* s_b2 = (float*)(sm + B2F);
    float* s_b3 = (float*)(sm + B3F);

    const int tid = threadIdx.x;
    const int wp = tid >> 5, l = tid & 31;
    const int q8 = l & 7;    // L3: output pair (2q8, 2q8+1)
    const int g  = l >> 3;   // L3: sample-pair group (pairs 4g..4g+3)

    u64* s_in = sm + ACT + wp * WARP_U64;     // [16][IN_STR]
    u64* s_h  = s_in + 16 * IN_STR;           // [16][H_STR]

    const long sbase = (long)blockIdx.x * TPB + wp * 32;

    u64 acc0[16], acc1[16];

    for (int node = 0; node < NNODES; ++node) {
        const bool root = (node < 4);
        const float *g1, *g2, *g3, *gb1, *gb2, *gb3;
        if (root) {
            g1 = w_r1 + node * (16 * 64);
            g2 = w_r2 + node * (64 * 64);
            g3 = w_r3 + node * (64 * 16);
            gb1 = b_r1 + node * 64; gb2 = b_r2 + node * 64; gb3 = b_r3 + node * 16;
        } else {
            const int j = node - 4;
            g1 = w_i1 + j * (80 * 64);
            g2 = w_i2 + j * (64 * 64);
            g3 = w_i3 + j * (64 * 16);
            gb1 = b_i1 + j * 64; gb2 = b_i2 + j * 64; gb3 = b_i3 + j * 16;
        }

        __syncthreads();   // all warps finished reading previous node's weights

        // ---- stage weights: w1, w2 duplicated as (w,w) u64; w3 plain ----
        {
            const int n1 = root ? 512 : 2560;           // float2 count of w1
            const float2* f1 = (const float2*)g1;
            for (int i = tid; i < n1; i += TPB) {
                float2 v = f1[i];
                w1d[2 * i]     = pk(v.x, v.x);
                w1d[2 * i + 1] = pk(v.y, v.y);
            }
            const float2* f2 = (const float2*)g2;
            for (int i = tid; i < 2048; i += TPB) {
                float2 v = f2[i];
                w2d[2 * i]     = pk(v.x, v.x);
                w2d[2 * i + 1] = pk(v.y, v.y);
            }
            for (int i = tid; i < 256; i += TPB)
                ((float4*)s_w3)[i] = ((const float4*)g3)[i];
            if (tid < 64) { s_b1[tid] = gb1[tid]; s_b2[tid] = gb2[tid]; }
            if (tid < 16) s_b3[tid] = gb3[tid];
        }
        // ---- stage u slice: lane l = sample sbase+l -> pair layout ----
        {
            const float* up = u + (sbase + l) * (NNODES * 16) + node * 16;
            float* inf = (float*)(s_in + ((l >> 1)) * IN_STR + 64);
            const int c = l & 1;
            #pragma unroll
            for (int dd = 0; dd < 16; dd += 4) {
                float4 v4 = *(const float4*)(up + dd);
                inf[(dd + 0) * 2 + c] = v4.x;
                inf[(dd + 1) * 2 + c] = v4.y;
                inf[(dd + 2) * 2 + c] = v4.z;
                inf[(dd + 3) * 2 + c] = v4.w;
            }
        }
        __syncthreads();

        // ---- pipelined inner block ----
        // W: dup'd u64 weights, row stride 64 u64; lane reads (col 2l, 2l+1).
        // act: u64 sample-pairs, rows of `stride`, column base already applied.
        auto mm = [&](const u64* W, const u64* act, int stride, int kcount) {
            const u64* wl = W + 2 * l;
            ulonglong2 wA = *(const ulonglong2*)(wl);           // k
            ulonglong2 wB = *(const ulonglong2*)(wl + 64);      // k+1
            ulonglong2 xa[8], xb[8];
            #pragma unroll
            for (int p = 0; p < 8; ++p)
                xa[p] = *(const ulonglong2*)(act + p * stride);
            #pragma unroll 1
            for (int kk = 0; kk < kcount; kk += 2) {
                #pragma unroll
                for (int p = 0; p < 8; ++p)
                    xb[p] = *(const ulonglong2*)(act + (p + 8) * stride + kk);
                ulonglong2 nA = *(const ulonglong2*)(wl + (kk + 2) * 64);
                ulonglong2 nB = *(const ulonglong2*)(wl + (kk + 3) * 64);
                #pragma unroll
                for (int p = 0; p < 8; ++p) {
                    acc0[p] = fma2(xa[p].x, wA.x, acc0[p]);
                    acc1[p] = fma2(xa[p].x, wA.y, acc1[p]);
                    acc0[p] = fma2(xa[p].y, wB.x, acc0[p]);
                    acc1[p] = fma2(xa[p].y, wB.y, acc1[p]);
                }
                #pragma unroll
                for (int p = 0; p < 8; ++p)
                    xa[p] = *(const ulonglong2*)(act + p * stride + kk + 2);
                #pragma unroll
                for (int p = 0; p < 8; ++p) {
                    acc0[8 + p] = fma2(xb[p].x, wA.x, acc0[8 + p]);
                    acc1[8 + p] = fma2(xb[p].x, wA.y, acc1[8 + p]);
                    acc0[8 + p] = fma2(xb[p].y, wB.x, acc0[8 + p]);
                    acc1[8 + p] = fma2(xb[p].y, wB.y, acc1[8 + p]);
                }
                wA = nA; wB = nB;
            }
        };

        auto relu_store = [&]() {
            #pragma unroll
            for (int p = 0; p < 16; ++p) {
                ulonglong2 r;
                r.x = relu2(acc0[p]); r.y = relu2(acc1[p]);
                *(ulonglong2*)(s_h + p * H_STR + 2 * l) = r;
            }
        };

        // ---- layer 1 ----
        {
            float2 bb = *(const float2*)(s_b1 + 2 * l);
            const u64 d0 = dup2(bb.x), d1 = dup2(bb.y);
            #pragma unroll
            for (int p = 0; p < 16; ++p) { acc0[p] = d0; acc1[p] = d1; }
        }
        if (!root) {
            #pragma unroll 1
            for (int q = 0; q < 4; ++q)
                mm(w1d + (q * 16) * 64, s_in + ((node + q) & 3) * 16, IN_STR, 16);
            mm(w1d + 64 * 64, s_in + 64, IN_STR, 16);
        } else {
            mm(w1d, s_in + 64, IN_STR, 16);
        }
        relu_store();
        __syncwarp();

        // ---- layer 2 ----
        {
            float2 bb = *(const float2*)(s_b2 + 2 * l);
            const u64 d0 = dup2(bb.x), d1 = dup2(bb.y);
            #pragma unroll
            for (int p = 0; p < 16; ++p) { acc0[p] = d0; acc1[p] = d1; }
        }
        mm(w2d, s_h, H_STR, 64);
        __syncwarp();          // all lanes done reading old h
        relu_store();
        __syncwarp();

        // ---- layer 3: lane (q8,g) -> cols (2q8, 2q8+1), pairs 4g..4g+3 ----
        u64 c0[4], c1[4];
        {
            const u64 d0 = dup2(s_b3[2 * q8]), d1 = dup2(s_b3[2 * q8 + 1]);
            #pragma unroll
            for (int pl = 0; pl < 4; ++pl) { c0[pl] = d0; c1[pl] = d1; }
        }
        #pragma unroll 1
        for (int kk = 0; kk < 64; kk += 2) {
            float2 wa = *(const float2*)(s_w3 + kk * 16 + 2 * q8);
            float2 wb = *(const float2*)(s_w3 + (kk + 1) * 16 + 2 * q8);
            const u64 A0 = dup2(wa.x), A1 = dup2(wa.y);
            const u64 B0 = dup2(wb.x), B1 = dup2(wb.y);
            #pragma unroll
            for (int pl = 0; pl < 4; ++pl) {
                ulonglong2 xx =
                    *(const ulonglong2*)(s_h + (4 * g + pl) * H_STR + kk);
                c0[pl] = fma2(xx.x, A0, c0[pl]);
                c0[pl] = fma2(xx.y, B0, c0[pl]);
                c1[pl] = fma2(xx.x, A1, c1[pl]);
                c1[pl] = fma2(xx.y, B1, c1[pl]);
            }
        }

        // ---- emit: logits to gmem, thresholded bits into parent ring ----
        const int slot = (node & 3) * 16;
        #pragma unroll
        for (int pl = 0; pl < 4; ++pl) {
            const int p = 4 * g + pl;
            const long s0 = sbase + 2 * p;
            float v00, v01, v10, v11;
            unpk(c0[pl], v00, v01);   // col 2q8, samples (2p, 2p+1)
            unpk(c1[pl], v10, v11);   // col 2q8+1
            float* o0 = out + s0 * (NNODES * 16) + node * 16 + 2 * q8;
            float* o1 = o0 + (NNODES * 16);
            o0[0] = v00; o0[1] = v10;
            o1[0] = v01; o1[1] = v11;
            s_in[p * IN_STR + slot + 2 * q8] =
                pk(v00 > 0.5f ? 1.0f : 0.0f, v01 > 0.5f ? 1.0f : 0.0f);
            s_in[p * IN_STR + slot + 2 * q8 + 1] =
                pk(v10 > 0.5f ? 1.0f : 0.0f, v11 > 0.5f ? 1.0f : 0.0f);
        }
    }
}

extern "C" void kernel_launch(void* const* d_in, const int* in_sizes, int n_in,
                              void* d_out, int out_size) {
    (void)in_sizes; (void)n_in; (void)out_size;
    cudaFuncSetAttribute(ncm_kernel, cudaFuncAttributeMaxDynamicSharedMemorySize,
                         SMEM_BYTES);
    ncm_kernel<<<NBLK, TPB, SMEM_BYTES>>>(
        (const float*)d_in[0],
        (const float*)d_in[1], (const float*)d_in[2],
        (const float*)d_in[3], (const float*)d_in[4],
        (const float*)d_in[5], (const float*)d_in[6],
        (const float*)d_in[7], (const float*)d_in[8],
        (const float*)d_in[9], (const float*)d_in[10],
        (const float*)d_in[11], (const float*)d_in[12],
        (float*)d_out);
}

// round 5
// speedup vs baseline: 1.2152x; 1.2152x over previous
#include <cuda_runtime.h>

// NCM R5: R2 inner loop, half warp-tile (16 samples = 8 f32x2 pairs/warp),
// u aliased into h buffer, no pads -> 104.6 KB/CTA -> 2 CTAs/SM (4 warps/SMSP).
// 256 CTAs x 256 threads.

#define TPB    256
#define NBLK   256
#define NNODES 32

typedef unsigned long long u64;

__device__ __forceinline__ u64 fma2(u64 a, u64 b, u64 c) {
    u64 d; asm("fma.rn.f32x2 %0,%1,%2,%3;" : "=l"(d) : "l"(a), "l"(b), "l"(c));
    return d;
}
__device__ __forceinline__ u64 dup2(float x) {
    u64 d; asm("mov.b64 %0,{%1,%1};" : "=l"(d) : "f"(x)); return d;
}
__device__ __forceinline__ void unpk(u64 a, float& lo, float& hi) {
    asm("mov.b64 {%0,%1},%2;" : "=f"(lo), "=f"(hi) : "l"(a));
}
__device__ __forceinline__ u64 pk(float lo, float hi) {
    u64 d; asm("mov.b64 %0,{%1,%2};" : "=l"(d) : "f"(lo), "f"(hi)); return d;
}
__device__ __forceinline__ u64 relu2(u64 a) {
    float lo, hi; unpk(a, lo, hi);
    return pk(fmaxf(lo, 0.0f), fmaxf(hi, 0.0f));
}

// u64-unit SMEM offsets
#define W1F 0        // w1 floats: 80*64 f = 2560 u64
#define W2F 2560     // w2: 64*64 f = 2048 u64
#define W3F 4608     // w3: 64*16 f = 512 u64
#define B1F 5120     // 64 f = 32 u64
#define B2F 5152
#define B3F 5184     // 16 f = 8 u64
#define ACT 5192
// per-warp: ring u64[8][64] | h u64[8][64]  (u aliased into h cols 0..15)
#define WARP_U64 1024
#define SMEM_BYTES ((ACT + 8 * WARP_U64) * 8)   // 107072

__global__ void __launch_bounds__(TPB, 2) ncm_kernel(
    const float* __restrict__ u,
    const float* __restrict__ w_r1, const float* __restrict__ b_r1,
    const float* __restrict__ w_r2, const float* __restrict__ b_r2,
    const float* __restrict__ w_r3, const float* __restrict__ b_r3,
    const float* __restrict__ w_i1, const float* __restrict__ b_i1,
    const float* __restrict__ w_i2, const float* __restrict__ b_i2,
    const float* __restrict__ w_i3, const float* __restrict__ b_i3,
    float* __restrict__ out)
{
    extern __shared__ u64 sm[];
    float* s_w1 = (float*)(sm + W1F);
    float* s_w2 = (float*)(sm + W2F);
    float* s_w3 = (float*)(sm + W3F);
    float* s_b1 = (float*)(sm + B1F);
    float* s_b2 = (float*)(sm + B2F);
    float* s_b3 = (float*)(sm + B3F);

    const int tid = threadIdx.x;
    const int wp = tid >> 5, l = tid & 31;
    const int q8 = l & 7;    // L3: output dims (2q8, 2q8+1)
    const int g  = l >> 3;   // L3: pairs 2g, 2g+1

    u64* s_ring = sm + ACT + wp * WARP_U64;   // [8][64]: [pair][slot*16+dim]
    u64* s_h    = s_ring + 512;               // [8][64]; u lives in cols 0..15

    const long sbase = (long)blockIdx.x * 128 + wp * 16;

    u64 acc0[8], acc1[8];

    for (int node = 0; node < NNODES; ++node) {
        const bool root = (node < 4);
        const float *g1, *g2, *g3, *gb1, *gb2, *gb3;
        if (root) {
            g1 = w_r1 + node * (16 * 64);
            g2 = w_r2 + node * (64 * 64);
            g3 = w_r3 + node * (64 * 16);
            gb1 = b_r1 + node * 64; gb2 = b_r2 + node * 64; gb3 = b_r3 + node * 16;
        } else {
            const int j = node - 4;
            g1 = w_i1 + j * (80 * 64);
            g2 = w_i2 + j * (64 * 64);
            g3 = w_i3 + j * (64 * 16);
            gb1 = b_i1 + j * 64; gb2 = b_i2 + j * 64; gb3 = b_i3 + j * 16;
        }

        __syncthreads();   // all warps done with previous node's weights

        // ---- stage weights (coalesced float4) + biases ----
        {
            const int n1 = root ? (16 * 64 / 4) : (80 * 64 / 4);
            for (int i = tid; i < n1; i += TPB)
                ((float4*)s_w1)[i] = ((const float4*)g1)[i];
            for (int i = tid; i < 64 * 64 / 4; i += TPB)
                ((float4*)s_w2)[i] = ((const float4*)g2)[i];
            for (int i = tid; i < 64 * 16 / 4; i += TPB)
                ((float4*)s_w3)[i] = ((const float4*)g3)[i];
            if (tid < 64) { s_b1[tid] = gb1[tid]; s_b2[tid] = gb2[tid]; }
            if (tid < 16) s_b3[tid] = gb3[tid];
        }
        // ---- stage u (2 lanes per sample) into h-buffer cols 0..15 ----
        {
            const int sw = l >> 1;       // sample-in-warp 0..15
            const int hf = l & 1;        // dim half: 8*hf..8*hf+7
            const float* up = u + (sbase + sw) * (NNODES * 16) + node * 16 + 8 * hf;
            float* inf = (float*)(s_h + (sw >> 1) * 64);
            const int c = sw & 1;        // half of the f32x2 pair
            #pragma unroll
            for (int dd = 0; dd < 8; dd += 4) {
                float4 v4 = *(const float4*)(up + dd);
                inf[(8 * hf + dd + 0) * 2 + c] = v4.x;
                inf[(8 * hf + dd + 1) * 2 + c] = v4.y;
                inf[(8 * hf + dd + 2) * 2 + c] = v4.z;
                inf[(8 * hf + dd + 3) * 2 + c] = v4.w;
            }
        }
        __syncthreads();

        // R2-style inner block: weights W rows (this lane's cols 2l, 2l+1),
        // acts = broadcast u64 sample-pairs, rows of 64 u64, 2 k per iter.
        auto mm = [&](const float* W, const u64* act, int kcount) {
            #pragma unroll 1
            for (int kk = 0; kk < kcount; kk += 2) {
                float2 wa = *(const float2*)(W + kk * 64 + 2 * l);
                float2 wb = *(const float2*)(W + (kk + 1) * 64 + 2 * l);
                const u64 A0 = dup2(wa.x), A1 = dup2(wa.y);
                const u64 B0 = dup2(wb.x), B1 = dup2(wb.y);
                #pragma unroll
                for (int p = 0; p < 8; ++p) {
                    ulonglong2 xx = *(const ulonglong2*)(act + p * 64 + kk);
                    acc0[p] = fma2(xx.x, A0, acc0[p]);
                    acc0[p] = fma2(xx.y, B0, acc0[p]);
                    acc1[p] = fma2(xx.x, A1, acc1[p]);
                    acc1[p] = fma2(xx.y, B1, acc1[p]);
                }
            }
        };

        auto relu_store = [&]() {
            #pragma unroll
            for (int p = 0; p < 8; ++p) {
                ulonglong2 r;
                r.x = relu2(acc0[p]); r.y = relu2(acc1[p]);
                *(ulonglong2*)(s_h + p * 64 + 2 * l) = r;
            }
        };

        // ---- layer 1 ----
        {
            float2 bb = *(const float2*)(s_b1 + 2 * l);
            const u64 d0 = dup2(bb.x), d1 = dup2(bb.y);
            #pragma unroll
            for (int p = 0; p < 8; ++p) { acc0[p] = d0; acc1[p] = d1; }
        }
        if (!root) {
            #pragma unroll 1
            for (int q = 0; q < 4; ++q)
                mm(s_w1 + (q * 16) * 64, s_ring + ((node + q) & 3) * 16, 16);
            mm(s_w1 + 64 * 64, s_h, 16);    // u part (h cols 0..15)
        } else {
            mm(s_w1, s_h, 16);
        }
        __syncwarp();      // all u reads done before h overwrites cols 0..15
        relu_store();
        __syncwarp();

        // ---- layer 2 (in-place h) ----
        {
            float2 bb = *(const float2*)(s_b2 + 2 * l);
            const u64 d0 = dup2(bb.x), d1 = dup2(bb.y);
            #pragma unroll
            for (int p = 0; p < 8; ++p) { acc0[p] = d0; acc1[p] = d1; }
        }
        mm(s_w2, s_h, 64);
        __syncwarp();      // all lanes done reading old h
        relu_store();
        __syncwarp();

        // ---- layer 3: lane (q8,g) -> dims (2q8,2q8+1), pairs 2g,2g+1 ----
        u64 c0[2], c1[2];
        {
            const u64 d0 = dup2(s_b3[2 * q8]), d1 = dup2(s_b3[2 * q8 + 1]);
            c0[0] = d0; c0[1] = d0; c1[0] = d1; c1[1] = d1;
        }
        #pragma unroll 1
        for (int kk = 0; kk < 64; kk += 2) {
            float2 wa = *(const float2*)(s_w3 + kk * 16 + 2 * q8);
            float2 wb = *(const float2*)(s_w3 + (kk + 1) * 16 + 2 * q8);
            const u64 A0 = dup2(wa.x), A1 = dup2(wa.y);
            const u64 B0 = dup2(wb.x), B1 = dup2(wb.y);
            #pragma unroll
            for (int pl = 0; pl < 2; ++pl) {
                ulonglong2 xx =
                    *(const ulonglong2*)(s_h + (2 * g + pl) * 64 + kk);
                c0[pl] = fma2(xx.x, A0, c0[pl]);
                c0[pl] = fma2(xx.y, B0, c0[pl]);
                c1[pl] = fma2(xx.x, A1, c1[pl]);
                c1[pl] = fma2(xx.y, B1, c1[pl]);
            }
        }

        // ---- emit: logits (float2, coalesced) + thresholded ring bits ----
        const int slot = (node & 3) * 16;
        #pragma unroll
        for (int pl = 0; pl < 2; ++pl) {
            const int p = 2 * g + pl;
            const long s0 = sbase + 2 * p;
            float v00, v01, v10, v11;
            unpk(c0[pl], v00, v01);   // dim 2q8,  samples (2p, 2p+1)
            unpk(c1[pl], v10, v11);   // dim 2q8+1
            float2* o0 = (float2*)(out + s0 * (NNODES * 16) + node * 16 + 2 * q8);
            float2* o1 = (float2*)((float*)o0 + NNODES * 16);
            *o0 = make_float2(v00, v10);
            *o1 = make_float2(v01, v11);
            s_ring[p * 64 + slot + 2 * q8] =
                pk(v00 > 0.5f ? 1.0f : 0.0f, v01 > 0.5f ? 1.0f : 0.0f);
            s_ring[p * 64 + slot + 2 * q8 + 1] =
                pk(v10 > 0.5f ? 1.0f : 0.0f, v11 > 0.5f ? 1.0f : 0.0f);
        }
    }
}

extern "C" void kernel_launch(void* const* d_in, const int* in_sizes, int n_in,
                              void* d_out, int out_size) {
    (void)in_sizes; (void)n_in; (void)out_size;
    cudaFuncSetAttribute(ncm_kernel, cudaFuncAttributeMaxDynamicSharedMemorySize,
                         SMEM_BYTES);
    ncm_kernel<<<NBLK, TPB, SMEM_BYTES>>>(
        (const float*)d_in[0],
        (const float*)d_in[1], (const float*)d_in[2],
        (const float*)d_in[3], (const float*)d_in[4],
        (const float*)d_in[5], (const float*)d_in[6],
        (const float*)d_in[7], (const float*)d_in[8],
        (const float*)d_in[9], (const float*)d_in[10],
        (const float*)d_in[11], (const float*)d_in[12],
        (float*)d_out);
}